// round 9
// baseline (speedup 1.0000x reference)
#include <cuda_runtime.h>
#include <cuda_bf16.h>
#include <math.h>
#include <stdint.h>

// ---------------- problem constants ----------------
namespace {
constexpr int B_ = 4, C_ = 128, T_ = 1000, F_ = 65;
constexpr int H_ = 4, E_ = 8, DH = 32;
constexpr int T1 = 199;
constexpr int TC = 398;
constexpr int EF = E_ * F_;      // 520
constexpr int DF = DH * F_;      // 2080
constexpr int PLD = 416;         // padded K-stride for P / VfT
constexpr int NTFC = TC * F_;    // 25870
constexpr int NTFT = T_ * F_;    // 65000
constexpr float EPS = 1e-5f;
constexpr float QSCALE = 0.04385290096535146f;  // 1/sqrt(520)
}

// ---------------- scratch (__device__ globals; no-alloc rule) ----------------
// bf16 hi/lo pre-split GEMM operands
__device__ __align__(16) __nv_bfloat16 d_XTcH[(size_t)B_ * NTFC * C_];
__device__ __align__(16) __nv_bfloat16 d_XTcL[(size_t)B_ * NTFC * C_];
__device__ __align__(16) __nv_bfloat16 d_WKH[32 * C_],  d_WKL[32 * C_];
__device__ __align__(16) __nv_bfloat16 d_WVH[C_ * C_],  d_WVL[C_ * C_];
__device__ __align__(16) __nv_bfloat16 d_WpH[C_ * C_],  d_WpL[C_ * C_];
__device__ __align__(16) __nv_bfloat16 d_QfH[(size_t)H_ * B_ * T_ * EF];
__device__ __align__(16) __nv_bfloat16 d_QfL[(size_t)H_ * B_ * T_ * EF];
__device__ __align__(16) __nv_bfloat16 d_KfH[(size_t)H_ * B_ * TC * EF];
__device__ __align__(16) __nv_bfloat16 d_KfL[(size_t)H_ * B_ * TC * EF];
__device__ __align__(16) __nv_bfloat16 d_VfTH[(size_t)H_ * B_ * DF * PLD];
__device__ __align__(16) __nv_bfloat16 d_VfTL[(size_t)H_ * B_ * DF * PLD];
__device__ __align__(16) __nv_bfloat16 d_PH[(size_t)H_ * B_ * T_ * PLD];
__device__ __align__(16) __nv_bfloat16 d_PL[(size_t)H_ * B_ * T_ * PLD];
__device__ __align__(16) __nv_bfloat16 d_OH[(size_t)H_ * B_ * T_ * DF];  // [z,t,n'=f*32+dh]
__device__ __align__(16) __nv_bfloat16 d_OL[(size_t)H_ * B_ * T_ * DF];
// fp32 intermediates
__device__ __align__(16) float d_Yk[(size_t)B_ * 32 * NTFC];
__device__ __align__(16) float d_Yv[(size_t)B_ * C_ * NTFC];
__device__ __align__(16) float d_Vf[(size_t)H_ * B_ * TC * DF];   // [z,tc,n']
__device__ __align__(16) float d_P [(size_t)H_ * B_ * T_ * PLD];  // scores (pre-softmax)
__device__ __align__(16) float d_Yp[(size_t)B_ * C_ * NTFT];

// ---------------- helpers ----------------
__device__ __forceinline__ uint32_t smem_u32(const void* p) {
    uint32_t a;
    asm("{ .reg .u64 t; cvta.to.shared.u64 t, %1; cvt.u32.u64 %0, t; }" : "=r"(a) : "l"(p));
    return a;
}
__device__ __forceinline__ uint32_t pk2(float lo, float hi) {
    uint32_t r;
    asm("cvt.rn.bf16x2.f32 %0, %1, %2;" : "=r"(r) : "f"(hi), "f"(lo));
    return r;
}
__device__ __forceinline__ float bfhi(float x) {
    return __bfloat162float(__float2bfloat16(x));
}
__device__ __forceinline__ void cpa16(uint32_t sa, const void* ga, uint32_t sz) {
    asm volatile("cp.async.cg.shared.global [%0], [%1], 16, %2;"
                 :: "r"(sa), "l"(ga), "r"(sz) : "memory");
}
__device__ __forceinline__ void ldsm4(uint32_t& r0, uint32_t& r1, uint32_t& r2, uint32_t& r3,
                                      uint32_t addr) {
    asm volatile("ldmatrix.sync.aligned.m8n8.x4.shared.b16 {%0,%1,%2,%3}, [%4];"
                 : "=r"(r0), "=r"(r1), "=r"(r2), "=r"(r3) : "r"(addr));
}
__device__ __forceinline__ void mma16816(float* c, const uint32_t* a, uint32_t b0, uint32_t b1) {
    asm volatile(
        "mma.sync.aligned.m16n8k16.row.col.f32.bf16.bf16.f32 "
        "{%0,%1,%2,%3}, {%4,%5,%6,%7}, {%8,%9}, {%0,%1,%2,%3};"
        : "+f"(c[0]), "+f"(c[1]), "+f"(c[2]), "+f"(c[3])
        : "r"(a[0]), "r"(a[1]), "r"(a[2]), "r"(a[3]), "r"(b0), "r"(b1));
}

// ---------------- 1) pool + signed concat -> XTc bf16 hi/lo [b,(tc,f),c] ----------------
__global__ void __launch_bounds__(256) pool_xtc_kernel(
        const float* __restrict__ pos, const float* __restrict__ neg) {
    __shared__ float sm[F_ * 129];
    int tc = blockIdx.x, b = blockIdx.y;
    int tid = threadIdx.x;
    const float* src; float sg; int t0;
    if (tc < T1) { src = pos; sg =  0.1f; t0 = tc * 5; }
    else         { src = neg; sg = -0.1f; t0 = (tc - T1) * 5; }
    for (int idx = tid; idx < C_ * F_; idx += 256) {
        int c = idx / F_, f = idx - c * F_;
        const float* p = src + ((size_t)(b * C_ + c) * T_ + t0) * F_ + f;
        float s = 0.f;
#pragma unroll
        for (int k = 0; k < 10; k++) s += p[(size_t)k * F_];
        sm[f * 129 + c] = s * sg;
    }
    __syncthreads();
    size_t base = ((size_t)b * NTFC + (size_t)tc * F_) * C_;
    for (int o = tid; o < F_ * C_; o += 256) {
        int f = o >> 7, c = o & 127;
        float v = sm[f * 129 + c];
        float h = bfhi(v);
        d_XTcH[base + o] = __float2bfloat16(h);
        d_XTcL[base + o] = __float2bfloat16(v - h);
    }
}

// ---------------- 2) weight split (WK, WV, Wp) -> bf16 hi/lo ----------------
__global__ void wsplit_kernel(const float* __restrict__ WK, const float* __restrict__ WV,
                              const float* __restrict__ Wp) {
    int i = blockIdx.x * 256 + threadIdx.x;
    float v; __nv_bfloat16 *oh, *ol; int j;
    if (i < 4096)        { j = i;         v = WK[j]; oh = d_WKH; ol = d_WKL; }
    else if (i < 20480)  { j = i - 4096;  v = WV[j]; oh = d_WVH; ol = d_WVL; }
    else if (i < 36864)  { j = i - 20480; v = Wp[j]; oh = d_WpH; ol = d_WpL; }
    else return;
    float h = bfhi(v);
    oh[j] = __float2bfloat16(h);
    ol[j] = __float2bfloat16(v - h);
}

// ---------------- 3) Q branch: conv1x1 + PReLU + LN (fp32) -> QfH/QfL ----------------
__global__ void __launch_bounds__(104)
conv_ln_q(const float* __restrict__ xin, const float* __restrict__ W,
          const float* __restrict__ bias, const float* __restrict__ alpha,
          const float* __restrict__ gamma, const float* __restrict__ beta) {
    constexpr int OC = 32, GRP = 8, WS = 130, NTHR = 104;
    extern __shared__ float sm[];
    float* xs = sm;
    float* ws = sm + C_ * F_;
    __shared__ float s_sum[OC / GRP], s_sq[OC / GRP];

    int bid = blockIdx.x;
    int b = bid / T_, t = bid % T_;
    int tid = threadIdx.x;

    for (int i = tid; i < C_ * F_; i += NTHR) {
        int c = i / F_, f = i - c * F_;
        xs[i] = xin[((size_t)(b * C_ + c) * T_ + t) * F_ + f];
    }
    for (int i = tid; i < OC * C_; i += NTHR) ws[(i >> 7) * WS + (i & 127)] = W[i];
    if (tid < OC / GRP) { s_sum[tid] = 0.f; s_sq[tid] = 0.f; }
    __syncthreads();

    int ocg = tid / 13, fg = tid - ocg * 13;
    int oc0 = ocg * 4, f0 = fg * 5;

    float acc[4][5];
#pragma unroll
    for (int i = 0; i < 4; i++) {
        float bv = bias[oc0 + i];
#pragma unroll
        for (int j = 0; j < 5; j++) acc[i][j] = bv;
    }
    for (int c = 0; c < C_; c++) {
        float xv[5];
#pragma unroll
        for (int j = 0; j < 5; j++) xv[j] = xs[c * F_ + f0 + j];
#pragma unroll
        for (int i = 0; i < 4; i++) {
            float wv = ws[(oc0 + i) * WS + c];
#pragma unroll
            for (int j = 0; j < 5; j++) acc[i][j] = fmaf(wv, xv[j], acc[i][j]);
        }
    }

    int g = oc0 / GRP;
    float a = alpha[g];
    float ps = 0.f, pq = 0.f;
#pragma unroll
    for (int i = 0; i < 4; i++)
#pragma unroll
        for (int j = 0; j < 5; j++) {
            float v = acc[i][j];
            v = (v >= 0.f) ? v : a * v;
            acc[i][j] = v;
            ps += v; pq += v * v;
        }
    atomicAdd(&s_sum[g], ps);
    atomicAdd(&s_sq[g], pq);
    __syncthreads();

    const float invn = 1.f / (float)(GRP * F_);
    float mu  = s_sum[g] * invn;
    float var = s_sq[g] * invn - mu * mu;
    float rinv = rsqrtf(var + EPS);

#pragma unroll
    for (int i = 0; i < 4; i++) {
        int oc = oc0 + i;
#pragma unroll
        for (int j = 0; j < 5; j++) {
            int f = f0 + j;
            float v = (acc[i][j] - mu) * rinv * gamma[oc * F_ + f] + beta[oc * F_ + f];
            v *= QSCALE;
            size_t idx = ((size_t)((oc >> 3) * B_ + b) * T_ + t) * EF + (oc & 7) * F_ + f;
            float h = bfhi(v);
            d_QfH[idx] = __float2bfloat16(h);
            d_QfL[idx] = __float2bfloat16(v - h);
        }
    }
}

// ---------------- 4) bf16 pre-split tensor-core GEMM (cp.async pipeline) ----------------
// C[M,N] = A[M,K] * B[N,K]^T via 3 passes (hh + hl + lh), fp32 accumulate.
// BMODE: 0 = B rows K-major at BH/BL + z*sBz;  1 = proj gather from d_OH/d_OL (z = b)
// OUTMODE: 0 = fp32 C;  1 = bf16 hi/lo pair (CH, CL)
template <int BMODE, int OUTMODE>
__global__ void __launch_bounds__(256)
mma_gemm(const __nv_bfloat16* __restrict__ AH, const __nv_bfloat16* __restrict__ AL,
         const __nv_bfloat16* __restrict__ BH, const __nv_bfloat16* __restrict__ BL,
         float* __restrict__ Cf, __nv_bfloat16* __restrict__ CH, __nv_bfloat16* __restrict__ CL,
         int M, int NrowsB, int Kvalid, int Kchunks,
         int lda, int ldb, int ldc,
         long long sAz, long long sBz, long long sCz, int writeN) {
    extern __shared__ __align__(16) char smc[];
    uint32_t sb = smem_u32(smc);
    constexpr uint32_t TSB = 128u * 40u * 2u;   // 10240 B per tile; stage = 4 tiles

    int tid = threadIdx.x, lane = tid & 31, wid = tid >> 5;
    int wm = wid & 3, wn = wid >> 2;
    int z = blockIdx.z;
    const __nv_bfloat16* AHz = AH + sAz * z;
    const __nv_bfloat16* ALz = AL + sAz * z;
    const __nv_bfloat16* BHz = BH + sBz * z;
    const __nv_bfloat16* BLz = BL + sBz * z;
    int mBase = blockIdx.y * 128, nBase = blockIdx.x * 128;

    float acc[2][8][4];
#pragma unroll
    for (int i = 0; i < 2; i++)
#pragma unroll
        for (int j = 0; j < 8; j++)
#pragma unroll
            for (int k = 0; k < 4; k++) acc[i][j][k] = 0.f;

    auto issue = [&](int c) {
        int k0 = c * 32;
        uint32_t st = sb + (uint32_t)(c & 1) * 4 * TSB;
#pragma unroll
        for (int i = 0; i < 2; i++) {
            int idx = i * 256 + tid;            // 0..511
            int r = idx >> 2, q = idx & 3;
            int gk = k0 + q * 8;
            uint32_t soff = (uint32_t)(r * 80 + q * 16);
            // A
            int gra = mBase + r;
            uint32_t sa = (gra < M && gk < Kvalid) ? 16u : 0u;
            size_t aoff = (size_t)gra * lda + gk;
            cpa16(st + soff,        AHz + aoff, sa);
            cpa16(st + TSB + soff,  ALz + aoff, sa);
            // B
            int grb = nBase + r;
            uint32_t sbs;
            const __nv_bfloat16 *gbh, *gbl;
            if (BMODE == 0) {
                sbs = (grb < NrowsB && gk < Kvalid) ? 16u : 0u;
                size_t boff = (size_t)grb * ldb + gk;
                gbh = BHz + boff; gbl = BLz + boff;
            } else {
                sbs = (grb < NrowsB) ? 16u : 0u;
                int t = grb / 65, f = grb - t * 65;
                size_t boff = ((size_t)((c * B_ + z) * T_) + t) * DF + f * 32 + q * 8;
                gbh = d_OH + boff; gbl = d_OL + boff;
            }
            cpa16(st + 2 * TSB + soff, gbh, sbs);
            cpa16(st + 3 * TSB + soff, gbl, sbs);
        }
        asm volatile("cp.async.commit_group;" ::: "memory");
    };

    uint32_t aRow = (uint32_t)((wm * 32 + (lane & 15)) * 80 + ((lane >> 4) << 4));
    uint32_t bRow = (uint32_t)((wn * 64 + (lane & 15)) * 80 + ((lane >> 4) << 4));

    auto compute = [&](int s) {
        uint32_t st = sb + (uint32_t)s * 4 * TSB;
#pragma unroll
        for (int ks = 0; ks < 2; ks++) {
            uint32_t ah[2][4], al[2][4];
#pragma unroll
            for (int mi = 0; mi < 2; mi++) {
                uint32_t ad = st + aRow + (uint32_t)(mi * 1280 + ks * 32);
                ldsm4(ah[mi][0], ah[mi][1], ah[mi][2], ah[mi][3], ad);
                ldsm4(al[mi][0], al[mi][1], al[mi][2], al[mi][3], ad + TSB);
            }
#pragma unroll
            for (int j = 0; j < 4; j++) {
                uint32_t bd = st + 2 * TSB + bRow + (uint32_t)(j * 1280 + ks * 32);
                uint32_t h0, h1, h2, h3, l0, l1, l2, l3;
                ldsm4(h0, h1, h2, h3, bd);
                ldsm4(l0, l1, l2, l3, bd + TSB);
                mma16816(acc[0][2 * j],     ah[0], h0, h2);
                mma16816(acc[1][2 * j],     ah[1], h0, h2);
                mma16816(acc[0][2 * j + 1], ah[0], h1, h3);
                mma16816(acc[1][2 * j + 1], ah[1], h1, h3);
                mma16816(acc[0][2 * j],     ah[0], l0, l2);
                mma16816(acc[1][2 * j],     ah[1], l0, l2);
                mma16816(acc[0][2 * j + 1], ah[0], l1, l3);
                mma16816(acc[1][2 * j + 1], ah[1], l1, l3);
                mma16816(acc[0][2 * j],     al[0], h0, h2);
                mma16816(acc[1][2 * j],     al[1], h0, h2);
                mma16816(acc[0][2 * j + 1], al[0], h1, h3);
                mma16816(acc[1][2 * j + 1], al[1], h1, h3);
            }
        }
    };

    issue(0);
    for (int c = 0; c < Kchunks; c++) {
        if (c + 1 < Kchunks) {
            issue(c + 1);
            asm volatile("cp.async.wait_group 1;" ::: "memory");
        } else {
            asm volatile("cp.async.wait_group 0;" ::: "memory");
        }
        __syncthreads();
        compute(c & 1);
        __syncthreads();
    }

    // epilogue
    float* Cfz = Cf + sCz * z;
    __nv_bfloat16* CHz = CH + sCz * z;
    __nv_bfloat16* CLz = CL + sCz * z;
#pragma unroll
    for (int mi = 0; mi < 2; mi++) {
#pragma unroll
        for (int ni = 0; ni < 8; ni++) {
            int r0 = mBase + wm * 32 + mi * 16 + (lane >> 2);
            int col = nBase + wn * 64 + ni * 8 + ((lane & 3) << 1);
            if (col < writeN) {
#pragma unroll
                for (int hh = 0; hh < 2; hh++) {
                    int r = r0 + hh * 8;
                    if (r < M) {
                        float v0 = acc[mi][ni][hh * 2], v1 = acc[mi][ni][hh * 2 + 1];
                        if (OUTMODE == 0) {
                            *(float2*)(Cfz + (size_t)r * ldc + col) = make_float2(v0, v1);
                        } else {
                            float h0 = bfhi(v0), h1 = bfhi(v1);
                            *(uint32_t*)(CHz + (size_t)r * ldc + col) = pk2(h0, h1);
                            *(uint32_t*)(CLz + (size_t)r * ldc + col) = pk2(v0 - h0, v1 - h1);
                        }
                    }
                }
            }
        }
    }
}

// ---------------- 5) fused bias + PReLU + LN epilogue after conv GEMMs ----------------
// MODE: 1=K -> KfH/KfL   2=V -> d_Vf (n' = f*32+dh)   3=proj -> out
template <int OC, int NG, int MODE>
__global__ void __launch_bounds__(256)
ln_kernel(const float* __restrict__ Y, int ldn,
          const float* __restrict__ bias, const float* __restrict__ alpha,
          const float* __restrict__ gamma, const float* __restrict__ beta,
          float* __restrict__ outp) {
    constexpr int GR = OC / NG;
    constexpr int NEL = GR * F_;
    constexpr int TPG = 256 / NG;
    constexpr int Tx = (MODE == 3) ? T_ : TC;
    __shared__ float buf[OC * F_];
    __shared__ float s_sum[NG], s_sq[NG];

    int bid = blockIdx.x;
    int b = bid / Tx, t = bid % Tx;
    int tid = threadIdx.x;
    int g = tid / TPG, l = tid - g * TPG;

    if (tid < NG) { s_sum[tid] = 0.f; s_sq[tid] = 0.f; }
    __syncthreads();

    const float* Yb = Y + ((size_t)b * OC) * ldn + (size_t)t * F_;
    float a = alpha[(MODE == 3) ? 0 : g];
    float s = 0.f, q = 0.f;
    for (int j = l; j < NEL; j += TPG) {
        int r = j / F_;
        int f = j - r * F_;
        float v = Yb[(size_t)(g * GR + r) * ldn + f] + bias[g * GR + r];
        v = (v >= 0.f) ? v : a * v;
        buf[g * NEL + j] = v;
        s += v; q += v * v;
    }
#pragma unroll
    for (int o = 16; o > 0; o >>= 1) {
        s += __shfl_xor_sync(0xffffffffu, s, o);
        q += __shfl_xor_sync(0xffffffffu, q, o);
    }
    if ((tid & 31) == 0) { atomicAdd(&s_sum[g], s); atomicAdd(&s_sq[g], q); }
    __syncthreads();

    const float invn = 1.f / (float)NEL;
    float mu = s_sum[g] * invn;
    float var = s_sq[g] * invn - mu * mu;
    float rinv = rsqrtf(var + EPS);

    if (MODE == 2) {
        // iterate in output (n') order: n' = f*32 + dh ; buf/gamma index = dh*F + f
        for (int j2 = l; j2 < NEL; j2 += TPG) {
            int dh = j2 & 31, f = j2 >> 5;
            int jb = dh * F_ + f;
            float v = (buf[g * NEL + jb] - mu) * rinv * gamma[g * NEL + jb] + beta[g * NEL + jb];
            d_Vf[((size_t)(g * B_ + b) * TC + t) * DF + j2] = v;
        }
    } else {
        for (int j = l; j < NEL; j += TPG) {
            float v = (buf[g * NEL + j] - mu) * rinv * gamma[g * NEL + j] + beta[g * NEL + j];
            if (MODE == 1) {
                size_t idx = ((size_t)(g * B_ + b) * TC + t) * EF + j;
                float h = bfhi(v);
                d_KfH[idx] = __float2bfloat16(h);
                d_KfL[idx] = __float2bfloat16(v - h);
            } else {
                int r = j / F_, f = j - r * F_;
                outp[((size_t)(b * C_ + r) * T_ + t) * F_ + f] = v;
            }
        }
    }
}

// ---------------- 6) transpose Vf [z,tc,n'] -> VfTH/L [z,n',tc(pad416 zeros)] ----------------
__global__ void transpose_v_kernel() {
    __shared__ float tile[32][33];
    int z = blockIdx.z;
    int n0 = blockIdx.x * 32, t0 = blockIdx.y * 32;
    int tx = threadIdx.x, ty = threadIdx.y;   // (32, 8)
#pragma unroll
    for (int i = ty; i < 32; i += 8) {
        int t = t0 + i;
        float v = 0.f;
        if (t < TC) v = d_Vf[((size_t)z * TC + t) * DF + n0 + tx];
        tile[i][tx] = v;
    }
    __syncthreads();
#pragma unroll
    for (int i = ty; i < 32; i += 8) {
        int n = n0 + i, t = t0 + tx;
        float v = tile[tx][i];
        float h = bfhi(v);
        size_t idx = ((size_t)z * DF + n) * PLD + t;
        d_VfTH[idx] = __float2bfloat16(h);
        d_VfTL[idx] = __float2bfloat16(v - h);
    }
}

// ---------------- 7) softmax on d_P rows -> PH/PL (pad cols zeroed) ----------------
__global__ void __launch_bounds__(128) softmax_kernel() {
    size_t row = blockIdx.x;
    const float* p = d_P + row * PLD;
    __nv_bfloat16* oh = d_PH + row * PLD;
    __nv_bfloat16* ol = d_PL + row * PLD;
    int tid = threadIdx.x;
    float v[4];
    int cnt = 0;
    float mx = -3.4e38f;
    for (int i = tid; i < TC; i += 128) { float x = p[i]; v[cnt++] = x; mx = fmaxf(mx, x); }
    __shared__ float smax[4], ssum[4];
#pragma unroll
    for (int o = 16; o > 0; o >>= 1) mx = fmaxf(mx, __shfl_xor_sync(0xffffffffu, mx, o));
    if ((tid & 31) == 0) smax[tid >> 5] = mx;
    __syncthreads();
    mx = fmaxf(fmaxf(smax[0], smax[1]), fmaxf(smax[2], smax[3]));
    float s = 0.f;
    for (int k = 0; k < cnt; k++) { float e = __expf(v[k] - mx); v[k] = e; s += e; }
#pragma unroll
    for (int o = 16; o > 0; o >>= 1) s += __shfl_xor_sync(0xffffffffu, s, o);
    if ((tid & 31) == 0) ssum[tid >> 5] = s;
    __syncthreads();
    s = ssum[0] + ssum[1] + ssum[2] + ssum[3];
    float inv = 1.f / s;
    cnt = 0;
    for (int i = tid; i < TC; i += 128) {
        float val = v[cnt++] * inv;
        float h = bfhi(val);
        oh[i] = __float2bfloat16(h);
        ol[i] = __float2bfloat16(val - h);
    }
    int ip = TC + tid;
    if (ip < PLD) { oh[ip] = __float2bfloat16(0.f); ol[ip] = __float2bfloat16(0.f); }
}

// ---------------- launch ----------------
extern "C" void kernel_launch(void* const* d_in, const int* in_sizes, int n_in,
                              void* d_out, int out_size) {
    (void)in_sizes; (void)n_in; (void)out_size;
    const float* batch = (const float*)d_in[0];
    const float* pos   = (const float*)d_in[1];
    const float* neg   = (const float*)d_in[2];
    const float* WQ  = (const float*)d_in[3];
    const float* bQ  = (const float*)d_in[4];
    const float* aQ  = (const float*)d_in[5];
    const float* gQ  = (const float*)d_in[6];
    const float* btQ = (const float*)d_in[7];
    const float* WK  = (const float*)d_in[8];
    const float* bK  = (const float*)d_in[9];
    const float* aK  = (const float*)d_in[10];
    const float* gK  = (const float*)d_in[11];
    const float* btK = (const float*)d_in[12];
    const float* WV  = (const float*)d_in[13];
    const float* bV  = (const float*)d_in[14];
    const float* aV  = (const float*)d_in[15];
    const float* gV  = (const float*)d_in[16];
    const float* btV = (const float*)d_in[17];
    const float* Wp  = (const float*)d_in[18];
    const float* bp  = (const float*)d_in[19];
    const float* ap  = (const float*)d_in[20];
    const float* gp  = (const float*)d_in[21];
    const float* btp = (const float*)d_in[22];
    float* out = (float*)d_out;

    void *pXTcH, *pXTcL, *pWKH, *pWKL, *pWVH, *pWVL, *pWpH, *pWpL;
    void *pQfH, *pQfL, *pKfH, *pKfL, *pVfTH, *pVfTL, *pPH, *pPL, *pOH, *pOL;
    void *pYk, *pYv, *pYp, *pP;
    cudaGetSymbolAddress(&pXTcH, d_XTcH); cudaGetSymbolAddress(&pXTcL, d_XTcL);
    cudaGetSymbolAddress(&pWKH, d_WKH);   cudaGetSymbolAddress(&pWKL, d_WKL);
    cudaGetSymbolAddress(&pWVH, d_WVH);   cudaGetSymbolAddress(&pWVL, d_WVL);
    cudaGetSymbolAddress(&pWpH, d_WpH);   cudaGetSymbolAddress(&pWpL, d_WpL);
    cudaGetSymbolAddress(&pQfH, d_QfH);   cudaGetSymbolAddress(&pQfL, d_QfL);
    cudaGetSymbolAddress(&pKfH, d_KfH);   cudaGetSymbolAddress(&pKfL, d_KfL);
    cudaGetSymbolAddress(&pVfTH, d_VfTH); cudaGetSymbolAddress(&pVfTL, d_VfTL);
    cudaGetSymbolAddress(&pPH, d_PH);     cudaGetSymbolAddress(&pPL, d_PL);
    cudaGetSymbolAddress(&pOH, d_OH);     cudaGetSymbolAddress(&pOL, d_OL);
    cudaGetSymbolAddress(&pYk, d_Yk);     cudaGetSymbolAddress(&pYv, d_Yv);
    cudaGetSymbolAddress(&pYp, d_Yp);     cudaGetSymbolAddress(&pP, d_P);

    typedef const __nv_bfloat16* BFP;
    typedef __nv_bfloat16* BFPW;

    const size_t smQK = (size_t)(C_ * F_ + 32 * 130) * sizeof(float);
    const size_t smMMA = 2 * 4 * (128 * 40 * 2);   // 81,920 B
    cudaFuncSetAttribute(conv_ln_q, cudaFuncAttributeMaxDynamicSharedMemorySize, (int)smQK);
    cudaFuncSetAttribute(mma_gemm<0, 0>, cudaFuncAttributeMaxDynamicSharedMemorySize, (int)smMMA);
    cudaFuncSetAttribute(mma_gemm<0, 1>, cudaFuncAttributeMaxDynamicSharedMemorySize, (int)smMMA);
    cudaFuncSetAttribute(mma_gemm<1, 0>, cudaFuncAttributeMaxDynamicSharedMemorySize, (int)smMMA);

    // pool + concat -> XTc bf16 hi/lo
    pool_xtc_kernel<<<dim3(TC, B_), 256>>>(pos, neg);
    // weight splits
    wsplit_kernel<<<144, 256>>>(WK, WV, Wp);
    // Q branch
    conv_ln_q<<<B_ * T_, 104, smQK>>>(batch, WQ, bQ, aQ, gQ, btQ);

    {   // K conv GEMM: Yk[b][oc<32][ntf]
        dim3 g((NTFC + 127) / 128, 1, B_);
        mma_gemm<0, 0><<<g, 256, smMMA>>>((BFP)pWKH, (BFP)pWKL, (BFP)pXTcH, (BFP)pXTcL,
            (float*)pYk, nullptr, nullptr,
            32, NTFC, C_, 4, C_, C_, NTFC,
            0LL, (long long)NTFC * C_, (long long)32 * NTFC, NTFC);
    }
    {   // V conv GEMM: Yv[b][oc<128][ntf]
        dim3 g((NTFC + 127) / 128, 1, B_);
        mma_gemm<0, 0><<<g, 256, smMMA>>>((BFP)pWVH, (BFP)pWVL, (BFP)pXTcH, (BFP)pXTcL,
            (float*)pYv, nullptr, nullptr,
            C_, NTFC, C_, 4, C_, C_, NTFC,
            0LL, (long long)NTFC * C_, (long long)C_ * NTFC, NTFC);
    }
    // K / V epilogues
    ln_kernel<32, 4, 1><<<B_ * TC, 256>>>((const float*)pYk, NTFC, bK, aK, gK, btK, nullptr);
    ln_kernel<128, 4, 2><<<B_ * TC, 256>>>((const float*)pYv, NTFC, bV, aV, gV, btV, nullptr);
    {   // Vf -> VfT bf16 (K-major for PV B operand)
        dim3 g(DF / 32, PLD / 32, H_ * B_);
        transpose_v_kernel<<<g, dim3(32, 8)>>>();
    }
    {   // scores: P = Qf @ Kf^T (fp32 out)
        dim3 g(4, 8, H_ * B_);
        mma_gemm<0, 0><<<g, 256, smMMA>>>((BFP)pQfH, (BFP)pQfL, (BFP)pKfH, (BFP)pKfL,
            (float*)pP, nullptr, nullptr,
            T_, TC, EF, 17, EF, EF, PLD,
            (long long)T_ * EF, (long long)TC * EF, (long long)T_ * PLD, PLD);
    }
    softmax_kernel<<<H_ * B_ * T_, 128>>>();
    {   // attention out: O' = P @ VfT^T  (bf16 hi/lo out, layout [z,t,n'=f*32+dh])
        dim3 g((DF + 127) / 128, 8, H_ * B_);
        mma_gemm<0, 1><<<g, 256, smMMA>>>((BFP)pPH, (BFP)pPL, (BFP)pVfTH, (BFP)pVfTL,
            nullptr, (BFPW)pOH, (BFPW)pOL,
            T_, DF, PLD, 13, PLD, PLD, DF,
            (long long)T_ * PLD, (long long)DF * PLD, (long long)T_ * DF, DF);
    }
    {   // proj GEMM (B gathered from O'): Yp[b][e][ntf]
        dim3 g((NTFT + 127) / 128, 1, B_);
        mma_gemm<1, 0><<<g, 256, smMMA>>>((BFP)pWpH, (BFP)pWpL, nullptr, nullptr,
            (float*)pYp, nullptr, nullptr,
            C_, NTFT, C_, 4, C_, 0, NTFT,
            0LL, 0LL, (long long)C_ * NTFT, NTFT);
    }
    // proj epilogue -> final output
    ln_kernel<128, 1, 3><<<B_ * T_, 256>>>((const float*)pYp, NTFT, bp, ap, gp, btp, out);
}

// round 14
// speedup vs baseline: 1.4089x; 1.4089x over previous
#include <cuda_runtime.h>
#include <cuda_bf16.h>
#include <math.h>
#include <stdint.h>

// ---------------- problem constants ----------------
namespace {
constexpr int B_ = 4, C_ = 128, T_ = 1000, F_ = 65;
constexpr int H_ = 4, E_ = 8, DH = 32;
constexpr int T1 = 199;          // pooled length per sign
constexpr int TC = 398;          // 2*T1
constexpr int NB5 = 200;         // number of 5-wide blocks along T
constexpr int EF = E_ * F_;      // 520
constexpr int DF = DH * F_;      // 2080
constexpr int PLD = 416;         // padded K-stride for P / VfT
constexpr int NTFC = TC * F_;    // 25870
constexpr int NTFT = T_ * F_;    // 65000
constexpr float EPS = 1e-5f;
constexpr float QSCALE = 0.04385290096535146f;  // 1/sqrt(520)
}

// ---------------- scratch (__device__ globals; no-alloc rule) ----------------
__device__ __align__(16) float d_tmpP[(size_t)B_ * C_ * NB5 * F_];  // 5-sums pos
__device__ __align__(16) float d_tmpN[(size_t)B_ * C_ * NB5 * F_];  // 5-sums neg
__device__ __align__(16) float d_XTc [(size_t)B_ * NTFC * C_];      // [b,(tc,f),c]
__device__ __align__(16) float d_Yk  [(size_t)B_ * 32 * NTFC];      // [b,oc,(tc,f)]
__device__ __align__(16) float d_Yv  [(size_t)B_ * 128 * NTFC];
__device__ __align__(16) float d_Qf  [(size_t)H_ * B_ * T_ * EF];   // [z, t, ef]
__device__ __align__(16) float d_Kf  [(size_t)H_ * B_ * TC * EF];
__device__ __align__(16) float d_Vf  [(size_t)H_ * B_ * TC * DF];
__device__ __align__(16) float d_VfT [(size_t)H_ * B_ * DF * PLD];  // [z, n, tc(pad0)]
__device__ __align__(16) float d_P   [(size_t)H_ * B_ * T_ * PLD];
__device__ __align__(16) float d_O   [(size_t)H_ * B_ * T_ * DF];   // [z, t, n]
__device__ __align__(16) float d_XTo [(size_t)B_ * NTFT * C_];      // [b,(t,f),c]
__device__ __align__(16) float d_Yp  [(size_t)B_ * 128 * NTFT];

// ---------------- helpers ----------------
__device__ __forceinline__ uint32_t smem_u32(const void* p) {
    uint32_t a;
    asm("{ .reg .u64 t; cvta.to.shared.u64 t, %1; cvt.u32.u64 %0, t; }" : "=r"(a) : "l"(p));
    return a;
}
__device__ __forceinline__ uint32_t pk2(float lo, float hi) {
    uint32_t r;
    asm("cvt.rn.bf16x2.f32 %0, %1, %2;" : "=r"(r) : "f"(hi), "f"(lo));
    return r;
}
__device__ __forceinline__ float bfhi(float x) {
    return __bfloat162float(__float2bfloat16(x));
}
__device__ __forceinline__ void ldsm4(uint32_t& r0, uint32_t& r1, uint32_t& r2, uint32_t& r3,
                                      uint32_t addr) {
    asm volatile("ldmatrix.sync.aligned.m8n8.x4.shared.b16 {%0,%1,%2,%3}, [%4];"
                 : "=r"(r0), "=r"(r1), "=r"(r2), "=r"(r3) : "r"(addr));
}
__device__ __forceinline__ void mma16816(float* c, const uint32_t* a, uint32_t b0, uint32_t b1) {
    asm volatile(
        "mma.sync.aligned.m16n8k16.row.col.f32.bf16.bf16.f32 "
        "{%0,%1,%2,%3}, {%4,%5,%6,%7}, {%8,%9}, {%0,%1,%2,%3};"
        : "+f"(c[0]), "+f"(c[1]), "+f"(c[2]), "+f"(c[3])
        : "r"(a[0]), "r"(a[1]), "r"(a[2]), "r"(a[3]), "r"(b0), "r"(b1));
}

// ---------------- 1a) non-overlapping 5-sums along T (input read once) ----------------
__global__ void __launch_bounds__(256) pool5_kernel(
        const float* __restrict__ pos, const float* __restrict__ neg) {
    constexpr int HALF = B_ * C_ * NB5 * F_;
    int idx = blockIdx.x * blockDim.x + threadIdx.x;
    if (idx >= 2 * HALF) return;
    const float* src = (idx < HALF) ? pos : neg;
    float* dst = (idx < HALF) ? d_tmpP : d_tmpN;
    int i = (idx < HALF) ? idx : idx - HALF;
    int f = i % F_;
    int r = i / F_;
    int j = r % NB5;  r /= NB5;
    int c = r % C_;
    int b = r / C_;
    const float* p = src + ((size_t)(b * C_ + c) * T_ + j * 5) * F_ + f;
    float s = p[0];
#pragma unroll
    for (int k = 1; k < 5; k++) s += p[(size_t)k * F_];
    dst[i] = s;
}

// ---------------- 1b) assemble XTc [b,(tc,f),c] from 5-sums (window = 2 blocks) ------
__global__ void xtc_kernel() {
    __shared__ float tl[32][33];
    int b = blockIdx.z;
    int c0 = blockIdx.y * 32, n0 = blockIdx.x * 32;
    int tx = threadIdx.x, ty = threadIdx.y;   // (32, 8)
#pragma unroll
    for (int i = ty; i < 32; i += 8) {
        int c = c0 + i, n = n0 + tx;
        float v = 0.f;
        if (n < NTFC) {
            int tc = n / F_, f = n - tc * F_;
            if (tc < T1) {
                const float* tp = d_tmpP + ((size_t)(b * C_ + c) * NB5 + tc) * F_ + f;
                v = 0.1f * (tp[0] + tp[F_]);
            } else {
                const float* tn = d_tmpN + ((size_t)(b * C_ + c) * NB5 + (tc - T1)) * F_ + f;
                v = -0.1f * (tn[0] + tn[F_]);
            }
        }
        tl[i][tx] = v;
    }
    __syncthreads();
#pragma unroll
    for (int i = ty; i < 32; i += 8) {
        int n = n0 + i;
        if (n < NTFC) d_XTc[((size_t)b * NTFC + n) * C_ + c0 + tx] = tl[tx][i];
    }
}

// ---------------- 2) Q branch: conv1x1 + PReLU + LN (fp32) ----------------
__global__ void __launch_bounds__(208)
conv_ln_q(const float* __restrict__ xin, const float* __restrict__ W,
          const float* __restrict__ bias, const float* __restrict__ alpha,
          const float* __restrict__ gamma, const float* __restrict__ beta) {
    constexpr int OC = 32, GRP = 8, WS = 130, NTHR = 208;
    extern __shared__ float sm[];
    float* xs = sm;                        // C_*F_
    float* ws = sm + C_ * F_;              // OC*WS
    __shared__ float s_sum[OC / GRP], s_sq[OC / GRP];

    int bid = blockIdx.x;
    int b = bid / T_, t = bid % T_;
    int tid = threadIdx.x;

    for (int i = tid; i < C_ * F_; i += NTHR) {
        int c = i / F_, f = i - c * F_;
        xs[i] = xin[((size_t)(b * C_ + c) * T_ + t) * F_ + f];
    }
    for (int i = tid; i < OC * C_; i += NTHR) ws[(i >> 7) * WS + (i & 127)] = W[i];
    if (tid < OC / GRP) { s_sum[tid] = 0.f; s_sq[tid] = 0.f; }
    __syncthreads();

    int ocg = tid / 13, fg = tid - ocg * 13;   // ocg 0..15
    int oc0 = ocg * 2, f0 = fg * 5;

    float acc[2][5];
#pragma unroll
    for (int i = 0; i < 2; i++) {
        float bv = bias[oc0 + i];
#pragma unroll
        for (int j = 0; j < 5; j++) acc[i][j] = bv;
    }
    for (int c = 0; c < C_; c++) {
        float xv[5];
#pragma unroll
        for (int j = 0; j < 5; j++) xv[j] = xs[c * F_ + f0 + j];
#pragma unroll
        for (int i = 0; i < 2; i++) {
            float wv = ws[(oc0 + i) * WS + c];
#pragma unroll
            for (int j = 0; j < 5; j++) acc[i][j] = fmaf(wv, xv[j], acc[i][j]);
        }
    }

    int g = oc0 / GRP;
    float a = alpha[g];
    float ps = 0.f, pq = 0.f;
#pragma unroll
    for (int i = 0; i < 2; i++)
#pragma unroll
        for (int j = 0; j < 5; j++) {
            float v = acc[i][j];
            v = (v >= 0.f) ? v : a * v;
            acc[i][j] = v;
            ps += v; pq += v * v;
        }
    atomicAdd(&s_sum[g], ps);
    atomicAdd(&s_sq[g], pq);
    __syncthreads();

    const float invn = 1.f / (float)(GRP * F_);
    float mu  = s_sum[g] * invn;
    float var = s_sq[g] * invn - mu * mu;
    float rinv = rsqrtf(var + EPS);

#pragma unroll
    for (int i = 0; i < 2; i++) {
        int oc = oc0 + i;
#pragma unroll
        for (int j = 0; j < 5; j++) {
            int f = f0 + j;
            float v = (acc[i][j] - mu) * rinv * gamma[oc * F_ + f] + beta[oc * F_ + f];
            d_Qf[((size_t)((oc >> 3) * B_ + b) * T_ + t) * EF + (oc & 7) * F_ + f] = v * QSCALE;
        }
    }
}

// ---------------- 3) shuffle d_O [z=(h,b)][t][dh*65+f] -> d_XTo [b][(t,f)][h*32+dh] ------
__global__ void __launch_bounds__(256) shuffle_o_kernel() {
    __shared__ float so[4 * DF];           // 33 KB
    int bid = blockIdx.x;
    int b = bid / T_, t = bid % T_;
    int tid = threadIdx.x;
    for (int i = tid; i < 4 * DF; i += 256) {
        int h = i / DF, rem = i - h * DF;
        so[i] = d_O[((size_t)(h * B_ + b) * T_ + t) * DF + rem];
    }
    __syncthreads();
    float* dst = d_XTo + ((size_t)b * NTFT + (size_t)t * F_) * C_;
    for (int i = tid; i < F_ * C_; i += 256) {
        int c = i & 127, f = i >> 7;
        int h = c >> 5, dh = c & 31;
        dst[(size_t)f * C_ + c] = so[h * DF + dh * F_ + f];
    }
}

// ---------------- 4) bf16-split tensor-core GEMM: C[M,N] = A[M,K] * B[N,K]^T ----------------
// 3x bf16 passes (hi*hi + hi*lo + lo*hi), fp32 accumulate. BM=BN=128, BK=32.
__global__ void __launch_bounds__(256)
mma_gemm(const float* __restrict__ A, const float* __restrict__ B, float* __restrict__ C,
         int M, int NrowsB, int Kvalid, int Kchunks,
         int lda, int ldb, int ldc,
         long long sAz, long long sBz, long long sCz, int writeN) {
    extern __shared__ __align__(16) char smc[];
    uint32_t sb = smem_u32(smc);
    constexpr uint32_t TSB = 128u * 40u * 2u;           // 10240 B per tile

    int tid = threadIdx.x, lane = tid & 31, wid = tid >> 5;
    int wm = wid & 3, wn = wid >> 2;
    int z = blockIdx.z;
    const float* Az = A + sAz * z;
    const float* Bz = B + sBz * z;
    float* Cz = C + sCz * z;
    int mBase = blockIdx.y * 128, nBase = blockIdx.x * 128;

    float acc[2][8][4];
#pragma unroll
    for (int i = 0; i < 2; i++)
#pragma unroll
        for (int j = 0; j < 8; j++)
#pragma unroll
            for (int k = 0; k < 4; k++) acc[i][j][k] = 0.f;

    const float4 f4z = make_float4(0.f, 0.f, 0.f, 0.f);
    float4 ra[4], rb[4];

    auto ldg = [&](int c) {
        int k0 = c * 32;
#pragma unroll
        for (int i = 0; i < 4; i++) {
            int idx = i * 256 + tid;
            int r = idx >> 3, gk = k0 + ((idx & 7) << 2);
            int gra = mBase + r;
            ra[i] = (gra < M && gk < Kvalid) ? *(const float4*)(Az + (size_t)gra * lda + gk) : f4z;
            int grb = nBase + r;
            rb[i] = (grb < NrowsB && gk < Kvalid) ? *(const float4*)(Bz + (size_t)grb * ldb + gk) : f4z;
        }
    };
    auto sts = [&](int s) {
        char* st = smc + (size_t)s * 4 * TSB;
#pragma unroll
        for (int i = 0; i < 4; i++) {
            int idx = i * 256 + tid;
            int r = idx >> 3, k = (idx & 7) << 2;
            uint32_t off = (uint32_t)(r * 80 + k * 2);
            float4 v = ra[i];
            float hx = bfhi(v.x), hy = bfhi(v.y), hz = bfhi(v.z), hw = bfhi(v.w);
            uint2 Hc = make_uint2(pk2(hx, hy), pk2(hz, hw));
            uint2 Lc = make_uint2(pk2(v.x - hx, v.y - hy), pk2(v.z - hz, v.w - hw));
            *(uint2*)(st + off)        = Hc;
            *(uint2*)(st + TSB + off)  = Lc;
            v = rb[i];
            hx = bfhi(v.x); hy = bfhi(v.y); hz = bfhi(v.z); hw = bfhi(v.w);
            Hc = make_uint2(pk2(hx, hy), pk2(hz, hw));
            Lc = make_uint2(pk2(v.x - hx, v.y - hy), pk2(v.z - hz, v.w - hw));
            *(uint2*)(st + 2 * TSB + off) = Hc;
            *(uint2*)(st + 3 * TSB + off) = Lc;
        }
    };

    uint32_t aRow = (uint32_t)((wm * 32 + (lane & 15)) * 80 + ((lane >> 4) << 4));
    uint32_t bRow = (uint32_t)((wn * 64 + (lane & 15)) * 80 + ((lane >> 4) << 4));

    auto compute = [&](int s) {
        uint32_t st = sb + (uint32_t)s * 4 * TSB;
#pragma unroll
        for (int ks = 0; ks < 2; ks++) {
            uint32_t ah[2][4], al[2][4];
#pragma unroll
            for (int mi = 0; mi < 2; mi++) {
                uint32_t ad = st + aRow + (uint32_t)(mi * 1280 + ks * 32);
                ldsm4(ah[mi][0], ah[mi][1], ah[mi][2], ah[mi][3], ad);
                ldsm4(al[mi][0], al[mi][1], al[mi][2], al[mi][3], ad + TSB);
            }
#pragma unroll
            for (int j = 0; j < 4; j++) {
                uint32_t bd = st + 2 * TSB + bRow + (uint32_t)(j * 1280 + ks * 32);
                uint32_t h0, h1, h2, h3, l0, l1, l2, l3;
                ldsm4(h0, h1, h2, h3, bd);
                ldsm4(l0, l1, l2, l3, bd + TSB);
                mma16816(acc[0][2 * j],     ah[0], h0, h2);
                mma16816(acc[1][2 * j],     ah[1], h0, h2);
                mma16816(acc[0][2 * j + 1], ah[0], h1, h3);
                mma16816(acc[1][2 * j + 1], ah[1], h1, h3);
                mma16816(acc[0][2 * j],     ah[0], l0, l2);
                mma16816(acc[1][2 * j],     ah[1], l0, l2);
                mma16816(acc[0][2 * j + 1], ah[0], l1, l3);
                mma16816(acc[1][2 * j + 1], ah[1], l1, l3);
                mma16816(acc[0][2 * j],     al[0], h0, h2);
                mma16816(acc[1][2 * j],     al[1], h0, h2);
                mma16816(acc[0][2 * j + 1], al[0], h1, h3);
                mma16816(acc[1][2 * j + 1], al[1], h1, h3);
            }
        }
    };

    ldg(0);
    sts(0);
    __syncthreads();
    for (int c = 0; c < Kchunks; c++) {
        bool nxt = (c + 1 < Kchunks);
        if (nxt) ldg(c + 1);
        compute(c & 1);
        if (nxt) {
            sts((c + 1) & 1);
            __syncthreads();
        }
    }

    // epilogue
#pragma unroll
    for (int mi = 0; mi < 2; mi++) {
#pragma unroll
        for (int ni = 0; ni < 8; ni++) {
            int r0 = mBase + wm * 32 + mi * 16 + (lane >> 2);
            int col = nBase + wn * 64 + ni * 8 + ((lane & 3) << 1);
            if (col < writeN) {
                if (r0 < M) {
                    float2 v = make_float2(acc[mi][ni][0], acc[mi][ni][1]);
                    *(float2*)(Cz + (size_t)r0 * ldc + col) = v;
                }
                if (r0 + 8 < M) {
                    float2 v = make_float2(acc[mi][ni][2], acc[mi][ni][3]);
                    *(float2*)(Cz + (size_t)(r0 + 8) * ldc + col) = v;
                }
            }
        }
    }
}

// ---------------- 5) fused bias + PReLU + LN epilogue after conv GEMMs ----------------
// MODE: 1=K -> d_Kf   2=V -> d_Vf   3=proj -> out
template <int OC, int NG, int MODE>
__global__ void __launch_bounds__(256)
ln_kernel(const float* __restrict__ Y, int ldn,
          const float* __restrict__ bias, const float* __restrict__ alpha,
          const float* __restrict__ gamma, const float* __restrict__ beta,
          float* __restrict__ outp) {
    constexpr int GR = OC / NG;
    constexpr int NEL = GR * F_;
    constexpr int TPG = 256 / NG;
    constexpr int Tx = (MODE == 3) ? T_ : TC;
    __shared__ float buf[OC * F_];
    __shared__ float s_sum[NG], s_sq[NG];

    int bid = blockIdx.x;
    int b = bid / Tx, t = bid % Tx;
    int tid = threadIdx.x;
    int g = tid / TPG, l = tid - g * TPG;

    if (tid < NG) { s_sum[tid] = 0.f; s_sq[tid] = 0.f; }
    __syncthreads();

    const float* Yb = Y + ((size_t)b * OC) * ldn + (size_t)t * F_;
    float a = alpha[(MODE == 3) ? 0 : g];
    float s = 0.f, q = 0.f;
    for (int j = l; j < NEL; j += TPG) {
        int r = j / F_;
        int f = j - r * F_;
        float v = Yb[(size_t)(g * GR + r) * ldn + f] + bias[g * GR + r];
        v = (v >= 0.f) ? v : a * v;
        buf[g * NEL + j] = v;
        s += v; q += v * v;
    }
#pragma unroll
    for (int o = 16; o > 0; o >>= 1) {
        s += __shfl_xor_sync(0xffffffffu, s, o);
        q += __shfl_xor_sync(0xffffffffu, q, o);
    }
    if ((tid & 31) == 0) { atomicAdd(&s_sum[g], s); atomicAdd(&s_sq[g], q); }
    __syncthreads();

    const float invn = 1.f / (float)NEL;
    float mu = s_sum[g] * invn;
    float var = s_sq[g] * invn - mu * mu;
    float rinv = rsqrtf(var + EPS);

    for (int j = l; j < NEL; j += TPG) {
        float v = (buf[g * NEL + j] - mu) * rinv * gamma[g * NEL + j] + beta[g * NEL + j];
        if (MODE == 1) {
            d_Kf[((size_t)(g * B_ + b) * TC + t) * EF + j] = v;
        } else if (MODE == 2) {
            d_Vf[((size_t)(g * B_ + b) * TC + t) * DF + j] = v;
        } else {
            int r = j / F_, f = j - r * F_;
            outp[((size_t)(b * C_ + r) * T_ + t) * F_ + f] = v;
        }
    }
}

// ---------------- 6) transpose Vf [z,tc,n] -> VfT [z,n,tc(pad 416, zeros)] ----------------
__global__ void transpose_v_kernel() {
    __shared__ float tile[32][33];
    int z = blockIdx.z;
    int n0 = blockIdx.x * 32, t0 = blockIdx.y * 32;
    int tx = threadIdx.x, ty = threadIdx.y;   // (32, 8)
#pragma unroll
    for (int i = ty; i < 32; i += 8) {
        int t = t0 + i;
        float v = 0.f;
        if (t < TC) v = d_Vf[((size_t)z * TC + t) * DF + n0 + tx];
        tile[i][tx] = v;
    }
    __syncthreads();
#pragma unroll
    for (int i = ty; i < 32; i += 8) {
        int n = n0 + i, t = t0 + tx;
        d_VfT[((size_t)z * DF + n) * PLD + t] = tile[tx][i];
    }
}

// ---------------- 7) softmax over tc (len 398), in place on d_P (ld 416) ----------------
__global__ void __launch_bounds__(128) softmax_kernel() {
    size_t row = blockIdx.x;
    float* p = d_P + row * PLD;
    int tid = threadIdx.x;
    float v[4];
    int cnt = 0;
    float mx = -3.4e38f;
    for (int i = tid; i < TC; i += 128) { float x = p[i]; v[cnt++] = x; mx = fmaxf(mx, x); }
    __shared__ float smax[4], ssum[4];
#pragma unroll
    for (int o = 16; o > 0; o >>= 1) mx = fmaxf(mx, __shfl_xor_sync(0xffffffffu, mx, o));
    if ((tid & 31) == 0) smax[tid >> 5] = mx;
    __syncthreads();
    mx = fmaxf(fmaxf(smax[0], smax[1]), fmaxf(smax[2], smax[3]));
    float s = 0.f;
    for (int k = 0; k < cnt; k++) { float e = __expf(v[k] - mx); v[k] = e; s += e; }
#pragma unroll
    for (int o = 16; o > 0; o >>= 1) s += __shfl_xor_sync(0xffffffffu, s, o);
    if ((tid & 31) == 0) ssum[tid >> 5] = s;
    __syncthreads();
    s = ssum[0] + ssum[1] + ssum[2] + ssum[3];
    float inv = 1.f / s;
    cnt = 0;
    for (int i = tid; i < TC; i += 128) p[i] = v[cnt++] * inv;
}

// ---------------- launch ----------------
extern "C" void kernel_launch(void* const* d_in, const int* in_sizes, int n_in,
                              void* d_out, int out_size) {
    (void)in_sizes; (void)n_in; (void)out_size;
    const float* batch = (const float*)d_in[0];
    const float* pos   = (const float*)d_in[1];
    const float* neg   = (const float*)d_in[2];
    const float* WQ  = (const float*)d_in[3];
    const float* bQ  = (const float*)d_in[4];
    const float* aQ  = (const float*)d_in[5];
    const float* gQ  = (const float*)d_in[6];
    const float* btQ = (const float*)d_in[7];
    const float* WK  = (const float*)d_in[8];
    const float* bK  = (const float*)d_in[9];
    const float* aK  = (const float*)d_in[10];
    const float* gK  = (const float*)d_in[11];
    const float* btK = (const float*)d_in[12];
    const float* WV  = (const float*)d_in[13];
    const float* bV  = (const float*)d_in[14];
    const float* aV  = (const float*)d_in[15];
    const float* gV  = (const float*)d_in[16];
    const float* btV = (const float*)d_in[17];
    const float* Wp  = (const float*)d_in[18];
    const float* bp  = (const float*)d_in[19];
    const float* ap  = (const float*)d_in[20];
    const float* gp  = (const float*)d_in[21];
    const float* btp = (const float*)d_in[22];
    float* out = (float*)d_out;

    void *pQf, *pKf, *pVfT, *pP, *pO, *pXTc, *pXTo, *pYk, *pYv, *pYp;
    cudaGetSymbolAddress(&pQf, d_Qf);
    cudaGetSymbolAddress(&pKf, d_Kf);
    cudaGetSymbolAddress(&pVfT, d_VfT);
    cudaGetSymbolAddress(&pP, d_P);
    cudaGetSymbolAddress(&pO, d_O);
    cudaGetSymbolAddress(&pXTc, d_XTc);
    cudaGetSymbolAddress(&pXTo, d_XTo);
    cudaGetSymbolAddress(&pYk, d_Yk);
    cudaGetSymbolAddress(&pYv, d_Yv);
    cudaGetSymbolAddress(&pYp, d_Yp);

    const size_t smQK = (size_t)(C_ * F_ + 32 * 130) * sizeof(float);
    const size_t smMMA = 2 * 4 * (128 * 40 * 2);   // 81,920 B
    cudaFuncSetAttribute(conv_ln_q, cudaFuncAttributeMaxDynamicSharedMemorySize, (int)smQK);
    cudaFuncSetAttribute(mma_gemm, cudaFuncAttributeMaxDynamicSharedMemorySize, (int)smMMA);

    {   // 5-sums (input read once)
        int total2 = 2 * B_ * C_ * NB5 * F_;
        pool5_kernel<<<(total2 + 255) / 256, 256>>>(pos, neg);
    }
    {   // assemble XTc [b,(tc,f),c] with sign + 1/10 scaling
        dim3 g((NTFC + 31) / 32, C_ / 32, B_);
        xtc_kernel<<<g, dim3(32, 8)>>>();
    }
    // Q branch (fp32 conv+LN fused, writes d_Qf with QSCALE folded)
    conv_ln_q<<<B_ * T_, 208, smQK>>>(batch, WQ, bQ, aQ, gQ, btQ);

    {   // K conv GEMM: Yk[b][oc<32][ntf] = WK @ XTc^T
        dim3 g((NTFC + 127) / 128, 1, B_);
        mma_gemm<<<g, 256, smMMA>>>(WK, (const float*)pXTc, (float*)pYk,
            32, NTFC, C_, 4, C_, C_, NTFC,
            0LL, (long long)NTFC * C_, (long long)32 * NTFC, NTFC);
    }
    {   // V conv GEMM: Yv[b][oc<128][ntf] = WV @ XTc^T
        dim3 g((NTFC + 127) / 128, 1, B_);
        mma_gemm<<<g, 256, smMMA>>>(WV, (const float*)pXTc, (float*)pYv,
            128, NTFC, C_, 4, C_, C_, NTFC,
            0LL, (long long)NTFC * C_, (long long)128 * NTFC, NTFC);
    }
    // K / V epilogues: bias + PReLU + LN -> Kf / Vf
    ln_kernel<32, 4, 1><<<B_ * TC, 256>>>((const float*)pYk, NTFC, bK, aK, gK, btK, nullptr);
    ln_kernel<128, 4, 2><<<B_ * TC, 256>>>((const float*)pYv, NTFC, bV, aV, gV, btV, nullptr);
    {   // Vf -> VfT (K-major B operand for PV), zero-padded to 416
        dim3 g(DF / 32, PLD / 32, H_ * B_);
        transpose_v_kernel<<<g, dim3(32, 8)>>>();
    }
    {   // scores: P = Qf @ Kf^T (M=1000, N=398 -> pad 416, K=520, 17 chunks)
        dim3 g(4, 8, H_ * B_);
        mma_gemm<<<g, 256, smMMA>>>(
            (const float*)pQf, (const float*)pKf, (float*)pP,
            T_, TC, EF, 17, EF, EF, PLD,
            (long long)T_ * EF, (long long)TC * EF, (long long)T_ * PLD, PLD);
    }
    softmax_kernel<<<H_ * B_ * T_, 128>>>();
    {   // attention out: O = P @ VfT^T (M=1000, N=2080, K=416 padded, 13 chunks)
        dim3 g((DF + 127) / 128, 8, H_ * B_);
        mma_gemm<<<g, 256, smMMA>>>(
            (const float*)pP, (const float*)pVfT, (float*)pO,
            T_, DF, PLD, 13, PLD, PLD, DF,
            (long long)T_ * PLD, (long long)DF * PLD, (long long)T_ * DF, DF);
    }
    // O -> K-major layout for proj GEMM
    shuffle_o_kernel<<<B_ * T_, 256>>>();
    {   // proj GEMM: Yp[b][e][ntf] = Wp @ XTo^T
        dim3 g((NTFT + 127) / 128, 1, B_);
        mma_gemm<<<g, 256, smMMA>>>(Wp, (const float*)pXTo, (float*)pYp,
            128, NTFT, C_, 4, C_, C_, NTFT,
            0LL, (long long)NTFT * C_, (long long)128 * NTFT, NTFT);
    }
    // proj epilogue: bias + PReLU + LN -> final output
    ln_kernel<128, 1, 3><<<B_ * T_, 256>>>((const float*)pYp, NTFT, bp, ap, gp, btp, out);
}

// round 15
// speedup vs baseline: 1.4140x; 1.0037x over previous
#include <cuda_runtime.h>
#include <cuda_bf16.h>
#include <math.h>
#include <stdint.h>

// ---------------- problem constants ----------------
namespace {
constexpr int B_ = 4, C_ = 128, T_ = 1000, F_ = 65;
constexpr int H_ = 4, E_ = 8, DH = 32;
constexpr int T1 = 199;
constexpr int TC = 398;
constexpr int NB5 = 200;
constexpr int EF = E_ * F_;      // 520
constexpr int DF = DH * F_;      // 2080
constexpr int PLD = 416;
constexpr int NTFC = TC * F_;    // 25870
constexpr int NTFT = T_ * F_;    // 65000
constexpr float EPS = 1e-5f;
constexpr float QSCALE = 0.04385290096535146f;  // 1/sqrt(520)
}

// ---------------- scratch (__device__ globals; no-alloc rule) ----------------
__device__ __align__(16) float d_tmpP[(size_t)B_ * C_ * NB5 * F_];
__device__ __align__(16) float d_tmpN[(size_t)B_ * C_ * NB5 * F_];
// bf16 hi/lo pre-split GEMM operands
__device__ __align__(16) __nv_bfloat16 d_XTcH[(size_t)B_ * NTFC * C_];
__device__ __align__(16) __nv_bfloat16 d_XTcL[(size_t)B_ * NTFC * C_];
__device__ __align__(16) __nv_bfloat16 d_WKH[32 * C_],  d_WKL[32 * C_];
__device__ __align__(16) __nv_bfloat16 d_WVH[C_ * C_],  d_WVL[C_ * C_];
__device__ __align__(16) __nv_bfloat16 d_WpH[C_ * C_],  d_WpL[C_ * C_];
__device__ __align__(16) __nv_bfloat16 d_QfH[(size_t)H_ * B_ * T_ * EF];
__device__ __align__(16) __nv_bfloat16 d_QfL[(size_t)H_ * B_ * T_ * EF];
__device__ __align__(16) __nv_bfloat16 d_KfH[(size_t)H_ * B_ * TC * EF];
__device__ __align__(16) __nv_bfloat16 d_KfL[(size_t)H_ * B_ * TC * EF];
__device__ __align__(16) __nv_bfloat16 d_VfTH[(size_t)H_ * B_ * DF * PLD];
__device__ __align__(16) __nv_bfloat16 d_VfTL[(size_t)H_ * B_ * DF * PLD];
__device__ __align__(16) __nv_bfloat16 d_PH[(size_t)H_ * B_ * T_ * PLD];
__device__ __align__(16) __nv_bfloat16 d_PL[(size_t)H_ * B_ * T_ * PLD];
__device__ __align__(16) __nv_bfloat16 d_OH[(size_t)H_ * B_ * T_ * DF];  // [z,t,n'=f*32+dh]
__device__ __align__(16) __nv_bfloat16 d_OL[(size_t)H_ * B_ * T_ * DF];
// fp32 intermediates
__device__ __align__(16) float d_Yk[(size_t)B_ * 32 * NTFC];
__device__ __align__(16) float d_Yv[(size_t)B_ * C_ * NTFC];
__device__ __align__(16) float d_Vf[(size_t)H_ * B_ * TC * DF];   // [z,tc,n']
__device__ __align__(16) float d_P [(size_t)H_ * B_ * T_ * PLD];
__device__ __align__(16) float d_Yp[(size_t)B_ * C_ * NTFT];

// ---------------- helpers ----------------
__device__ __forceinline__ uint32_t smem_u32(const void* p) {
    uint32_t a;
    asm("{ .reg .u64 t; cvta.to.shared.u64 t, %1; cvt.u32.u64 %0, t; }" : "=r"(a) : "l"(p));
    return a;
}
__device__ __forceinline__ uint32_t pk2(float lo, float hi) {
    uint32_t r;
    asm("cvt.rn.bf16x2.f32 %0, %1, %2;" : "=r"(r) : "f"(hi), "f"(lo));
    return r;
}
__device__ __forceinline__ float bfhi(float x) {
    return __bfloat162float(__float2bfloat16(x));
}
__device__ __forceinline__ void ldsm4(uint32_t& r0, uint32_t& r1, uint32_t& r2, uint32_t& r3,
                                      uint32_t addr) {
    asm volatile("ldmatrix.sync.aligned.m8n8.x4.shared.b16 {%0,%1,%2,%3}, [%4];"
                 : "=r"(r0), "=r"(r1), "=r"(r2), "=r"(r3) : "r"(addr));
}
__device__ __forceinline__ void mma16816(float* c, const uint32_t* a, uint32_t b0, uint32_t b1) {
    asm volatile(
        "mma.sync.aligned.m16n8k16.row.col.f32.bf16.bf16.f32 "
        "{%0,%1,%2,%3}, {%4,%5,%6,%7}, {%8,%9}, {%0,%1,%2,%3};"
        : "+f"(c[0]), "+f"(c[1]), "+f"(c[2]), "+f"(c[3])
        : "r"(a[0]), "r"(a[1]), "r"(a[2]), "r"(a[3]), "r"(b0), "r"(b1));
}

// ---------------- 1a) non-overlapping 5-sums along T ----------------
__global__ void __launch_bounds__(256) pool5_kernel(
        const float* __restrict__ pos, const float* __restrict__ neg) {
    constexpr int HALF = B_ * C_ * NB5 * F_;
    int idx = blockIdx.x * blockDim.x + threadIdx.x;
    if (idx >= 2 * HALF) return;
    const float* src = (idx < HALF) ? pos : neg;
    float* dst = (idx < HALF) ? d_tmpP : d_tmpN;
    int i = (idx < HALF) ? idx : idx - HALF;
    int f = i % F_;
    int r = i / F_;
    int j = r % NB5;  r /= NB5;
    int c = r % C_;
    int b = r / C_;
    const float* p = src + ((size_t)(b * C_ + c) * T_ + j * 5) * F_ + f;
    float s = p[0];
#pragma unroll
    for (int k = 1; k < 5; k++) s += p[(size_t)k * F_];
    dst[i] = s;
}

// ---------------- 1b) assemble XTc hi/lo [b,(tc,f),c] from 5-sums ----------------
__global__ void xtc_kernel() {
    __shared__ float tl[32][33];
    int b = blockIdx.z;
    int c0 = blockIdx.y * 32, n0 = blockIdx.x * 32;
    int tx = threadIdx.x, ty = threadIdx.y;   // (32, 8)
#pragma unroll
    for (int i = ty; i < 32; i += 8) {
        int c = c0 + i, n = n0 + tx;
        float v = 0.f;
        if (n < NTFC) {
            int tc = n / F_, f = n - tc * F_;
            if (tc < T1) {
                const float* tp = d_tmpP + ((size_t)(b * C_ + c) * NB5 + tc) * F_ + f;
                v = 0.1f * (tp[0] + tp[F_]);
            } else {
                const float* tn = d_tmpN + ((size_t)(b * C_ + c) * NB5 + (tc - T1)) * F_ + f;
                v = -0.1f * (tn[0] + tn[F_]);
            }
        }
        tl[i][tx] = v;
    }
    __syncthreads();
#pragma unroll
    for (int i = ty; i < 32; i += 8) {
        int n = n0 + i;
        if (n < NTFC) {
            float v = tl[tx][i];
            float h = bfhi(v);
            size_t o = ((size_t)b * NTFC + n) * C_ + c0 + tx;
            d_XTcH[o] = __float2bfloat16(h);
            d_XTcL[o] = __float2bfloat16(v - h);
        }
    }
}

// ---------------- 2) weight split (WK, WV, Wp) -> bf16 hi/lo ----------------
__global__ void wsplit_kernel(const float* __restrict__ WK, const float* __restrict__ WV,
                              const float* __restrict__ Wp) {
    int i = blockIdx.x * 256 + threadIdx.x;
    float v; __nv_bfloat16 *oh, *ol; int j;
    if (i < 4096)        { j = i;         v = WK[j]; oh = d_WKH; ol = d_WKL; }
    else if (i < 20480)  { j = i - 4096;  v = WV[j]; oh = d_WVH; ol = d_WVL; }
    else if (i < 36864)  { j = i - 20480; v = Wp[j]; oh = d_WpH; ol = d_WpL; }
    else return;
    float h = bfhi(v);
    oh[j] = __float2bfloat16(h);
    ol[j] = __float2bfloat16(v - h);
}

// ---------------- 3) Q branch: conv1x1 + PReLU + LN (fp32) -> QfH/QfL ----------------
__global__ void __launch_bounds__(208)
conv_ln_q(const float* __restrict__ xin, const float* __restrict__ W,
          const float* __restrict__ bias, const float* __restrict__ alpha,
          const float* __restrict__ gamma, const float* __restrict__ beta) {
    constexpr int OC = 32, GRP = 8, WS = 130, NTHR = 208;
    extern __shared__ float sm[];
    float* xs = sm;
    float* ws = sm + C_ * F_;
    __shared__ float s_sum[OC / GRP], s_sq[OC / GRP];

    int bid = blockIdx.x;
    int b = bid / T_, t = bid % T_;
    int tid = threadIdx.x;

    for (int i = tid; i < C_ * F_; i += NTHR) {
        int c = i / F_, f = i - c * F_;
        xs[i] = xin[((size_t)(b * C_ + c) * T_ + t) * F_ + f];
    }
    for (int i = tid; i < OC * C_; i += NTHR) ws[(i >> 7) * WS + (i & 127)] = W[i];
    if (tid < OC / GRP) { s_sum[tid] = 0.f; s_sq[tid] = 0.f; }
    __syncthreads();

    int ocg = tid / 13, fg = tid - ocg * 13;
    int oc0 = ocg * 2, f0 = fg * 5;

    float acc[2][5];
#pragma unroll
    for (int i = 0; i < 2; i++) {
        float bv = bias[oc0 + i];
#pragma unroll
        for (int j = 0; j < 5; j++) acc[i][j] = bv;
    }
    for (int c = 0; c < C_; c++) {
        float xv[5];
#pragma unroll
        for (int j = 0; j < 5; j++) xv[j] = xs[c * F_ + f0 + j];
#pragma unroll
        for (int i = 0; i < 2; i++) {
            float wv = ws[(oc0 + i) * WS + c];
#pragma unroll
            for (int j = 0; j < 5; j++) acc[i][j] = fmaf(wv, xv[j], acc[i][j]);
        }
    }

    int g = oc0 / GRP;
    float a = alpha[g];
    float ps = 0.f, pq = 0.f;
#pragma unroll
    for (int i = 0; i < 2; i++)
#pragma unroll
        for (int j = 0; j < 5; j++) {
            float v = acc[i][j];
            v = (v >= 0.f) ? v : a * v;
            acc[i][j] = v;
            ps += v; pq += v * v;
        }
    atomicAdd(&s_sum[g], ps);
    atomicAdd(&s_sq[g], pq);
    __syncthreads();

    const float invn = 1.f / (float)(GRP * F_);
    float mu  = s_sum[g] * invn;
    float var = s_sq[g] * invn - mu * mu;
    float rinv = rsqrtf(var + EPS);

#pragma unroll
    for (int i = 0; i < 2; i++) {
        int oc = oc0 + i;
#pragma unroll
        for (int j = 0; j < 5; j++) {
            int f = f0 + j;
            float v = (acc[i][j] - mu) * rinv * gamma[oc * F_ + f] + beta[oc * F_ + f];
            v *= QSCALE;
            size_t idx = ((size_t)((oc >> 3) * B_ + b) * T_ + t) * EF + (oc & 7) * F_ + f;
            float h = bfhi(v);
            d_QfH[idx] = __float2bfloat16(h);
            d_QfL[idx] = __float2bfloat16(v - h);
        }
    }
}

// ---------------- 4) pre-split bf16 tensor-core GEMM: C[M,N] = A[M,K] * B[N,K]^T ------
// 3 passes (hh + hl + lh), fp32 accumulate. BM=BN=128, BK=32. Register-staged LDG/STS.
// BMODE: 0 = B rows K-major;  1 = proj gather from d_OH/d_OL (z = b, chunk = head)
// OUTMODE: 0 = fp32 C;  1 = bf16 hi/lo pair
template <int BMODE, int OUTMODE>
__global__ void __launch_bounds__(256, 2)
mma_gemm(const __nv_bfloat16* __restrict__ AH, const __nv_bfloat16* __restrict__ AL,
         const __nv_bfloat16* __restrict__ BH, const __nv_bfloat16* __restrict__ BL,
         float* __restrict__ Cf, __nv_bfloat16* __restrict__ CH, __nv_bfloat16* __restrict__ CL,
         int M, int NrowsB, int Kvalid, int Kchunks,
         int lda, int ldb, int ldc,
         long long sAz, long long sBz, long long sCz, int writeN) {
    extern __shared__ __align__(16) char smc[];
    uint32_t sb = smem_u32(smc);
    constexpr uint32_t TSB = 128u * 40u * 2u;   // 10240 B per tile; stage = AH AL BH BL

    int tid = threadIdx.x, lane = tid & 31, wid = tid >> 5;
    int wm = wid & 3, wn = wid >> 2;
    int z = blockIdx.z;
    const __nv_bfloat16* AHz = AH + sAz * z;
    const __nv_bfloat16* ALz = AL + sAz * z;
    const __nv_bfloat16* BHz = BH + sBz * z;
    const __nv_bfloat16* BLz = BL + sBz * z;
    int mBase = blockIdx.y * 128, nBase = blockIdx.x * 128;

    float acc[2][8][4];
#pragma unroll
    for (int i = 0; i < 2; i++)
#pragma unroll
        for (int j = 0; j < 8; j++)
#pragma unroll
            for (int k = 0; k < 4; k++) acc[i][j][k] = 0.f;

    const uint4 z4 = make_uint4(0u, 0u, 0u, 0u);
    uint4 rah[2], ral[2], rbh[2], rbl[2];

    auto ldg = [&](int c) {
        int k0 = c * 32;
#pragma unroll
        for (int i = 0; i < 2; i++) {
            int idx = i * 256 + tid;              // 0..511
            int r = idx >> 2, q = idx & 3;        // row, 16B chunk (8 bf16)
            int gk = k0 + q * 8;
            int gra = mBase + r;
            bool oa = (gra < M) && (gk < Kvalid);
            size_t aoff = (size_t)gra * lda + gk;
            rah[i] = oa ? *(const uint4*)(AHz + aoff) : z4;
            ral[i] = oa ? *(const uint4*)(ALz + aoff) : z4;
            int grb = nBase + r;
            if (BMODE == 0) {
                bool ob = (grb < NrowsB) && (gk < Kvalid);
                size_t boff = (size_t)grb * ldb + gk;
                rbh[i] = ob ? *(const uint4*)(BHz + boff) : z4;
                rbl[i] = ob ? *(const uint4*)(BLz + boff) : z4;
            } else {
                bool ob = (grb < NrowsB);
                int t = grb / 65, f = grb - t * 65;
                size_t boff = ((size_t)((c * B_ + z) * T_) + t) * DF + f * 32 + q * 8;
                rbh[i] = ob ? *(const uint4*)(d_OH + boff) : z4;
                rbl[i] = ob ? *(const uint4*)(d_OL + boff) : z4;
            }
        }
    };
    auto sts = [&](int s) {
        char* st = smc + (size_t)s * 4 * TSB;
#pragma unroll
        for (int i = 0; i < 2; i++) {
            int idx = i * 256 + tid;
            int r = idx >> 2, q = idx & 3;
            uint32_t off = (uint32_t)(r * 80 + q * 16);
            *(uint4*)(st + off)           = rah[i];
            *(uint4*)(st + TSB + off)     = ral[i];
            *(uint4*)(st + 2 * TSB + off) = rbh[i];
            *(uint4*)(st + 3 * TSB + off) = rbl[i];
        }
    };

    uint32_t aRow = (uint32_t)((wm * 32 + (lane & 15)) * 80 + ((lane >> 4) << 4));
    uint32_t bRow = (uint32_t)((wn * 64 + (lane & 15)) * 80 + ((lane >> 4) << 4));

    auto compute = [&](int s) {
        uint32_t st = sb + (uint32_t)s * 4 * TSB;
#pragma unroll
        for (int ks = 0; ks < 2; ks++) {
            uint32_t ah[2][4], al[2][4];
#pragma unroll
            for (int mi = 0; mi < 2; mi++) {
                uint32_t ad = st + aRow + (uint32_t)(mi * 1280 + ks * 32);
                ldsm4(ah[mi][0], ah[mi][1], ah[mi][2], ah[mi][3], ad);
                ldsm4(al[mi][0], al[mi][1], al[mi][2], al[mi][3], ad + TSB);
            }
#pragma unroll
            for (int j = 0; j < 4; j++) {
                uint32_t bd = st + 2 * TSB + bRow + (uint32_t)(j * 1280 + ks * 32);
                uint32_t h0, h1, h2, h3, l0, l1, l2, l3;
                ldsm4(h0, h1, h2, h3, bd);
                ldsm4(l0, l1, l2, l3, bd + TSB);
                mma16816(acc[0][2 * j],     ah[0], h0, h2);
                mma16816(acc[1][2 * j],     ah[1], h0, h2);
                mma16816(acc[0][2 * j + 1], ah[0], h1, h3);
                mma16816(acc[1][2 * j + 1], ah[1], h1, h3);
                mma16816(acc[0][2 * j],     ah[0], l0, l2);
                mma16816(acc[1][2 * j],     ah[1], l0, l2);
                mma16816(acc[0][2 * j + 1], ah[0], l1, l3);
                mma16816(acc[1][2 * j + 1], ah[1], l1, l3);
                mma16816(acc[0][2 * j],     al[0], h0, h2);
                mma16816(acc[1][2 * j],     al[1], h0, h2);
                mma16816(acc[0][2 * j + 1], al[0], h1, h3);
                mma16816(acc[1][2 * j + 1], al[1], h1, h3);
            }
        }
    };

    ldg(0);
    sts(0);
    __syncthreads();
    for (int c = 0; c < Kchunks; c++) {
        bool nxt = (c + 1 < Kchunks);
        if (nxt) ldg(c + 1);
        compute(c & 1);
        if (nxt) {
            sts((c + 1) & 1);
            __syncthreads();
        }
    }

    // epilogue
    float* Cfz = (OUTMODE == 0) ? Cf + sCz * z : nullptr;
    __nv_bfloat16* CHz = (OUTMODE == 1) ? CH + sCz * z : nullptr;
    __nv_bfloat16* CLz = (OUTMODE == 1) ? CL + sCz * z : nullptr;
#pragma unroll
    for (int mi = 0; mi < 2; mi++) {
#pragma unroll
        for (int ni = 0; ni < 8; ni++) {
            int r0 = mBase + wm * 32 + mi * 16 + (lane >> 2);
            int col = nBase + wn * 64 + ni * 8 + ((lane & 3) << 1);
            if (col < writeN) {
#pragma unroll
                for (int hh = 0; hh < 2; hh++) {
                    int r = r0 + hh * 8;
                    if (r < M) {
                        float v0 = acc[mi][ni][hh * 2], v1 = acc[mi][ni][hh * 2 + 1];
                        if (OUTMODE == 0) {
                            *(float2*)(Cfz + (size_t)r * ldc + col) = make_float2(v0, v1);
                        } else {
                            float h0 = bfhi(v0), h1 = bfhi(v1);
                            *(uint32_t*)(CHz + (size_t)r * ldc + col) = pk2(h0, h1);
                            *(uint32_t*)(CLz + (size_t)r * ldc + col) = pk2(v0 - h0, v1 - h1);
                        }
                    }
                }
            }
        }
    }
}

// ---------------- 5) fused bias + PReLU + LN epilogue after conv GEMMs ----------------
// MODE: 1=K -> KfH/KfL   2=V -> d_Vf (n' = f*32+dh)   3=proj -> out
template <int OC, int NG, int MODE>
__global__ void __launch_bounds__(256)
ln_kernel(const float* __restrict__ Y, int ldn,
          const float* __restrict__ bias, const float* __restrict__ alpha,
          const float* __restrict__ gamma, const float* __restrict__ beta,
          float* __restrict__ outp) {
    constexpr int GR = OC / NG;
    constexpr int NEL = GR * F_;
    constexpr int TPG = 256 / NG;
    constexpr int Tx = (MODE == 3) ? T_ : TC;
    __shared__ float buf[OC * F_];
    __shared__ float s_sum[NG], s_sq[NG];

    int bid = blockIdx.x;
    int b = bid / Tx, t = bid % Tx;
    int tid = threadIdx.x;
    int g = tid / TPG, l = tid - g * TPG;

    if (tid < NG) { s_sum[tid] = 0.f; s_sq[tid] = 0.f; }
    __syncthreads();

    const float* Yb = Y + ((size_t)b * OC) * ldn + (size_t)t * F_;
    float a = alpha[(MODE == 3) ? 0 : g];
    float s = 0.f, q = 0.f;
    for (int j = l; j < NEL; j += TPG) {
        int r = j / F_;
        int f = j - r * F_;
        float v = Yb[(size_t)(g * GR + r) * ldn + f] + bias[g * GR + r];
        v = (v >= 0.f) ? v : a * v;
        buf[g * NEL + j] = v;
        s += v; q += v * v;
    }
#pragma unroll
    for (int o = 16; o > 0; o >>= 1) {
        s += __shfl_xor_sync(0xffffffffu, s, o);
        q += __shfl_xor_sync(0xffffffffu, q, o);
    }
    if ((tid & 31) == 0) { atomicAdd(&s_sum[g], s); atomicAdd(&s_sq[g], q); }
    __syncthreads();

    const float invn = 1.f / (float)NEL;
    float mu = s_sum[g] * invn;
    float var = s_sq[g] * invn - mu * mu;
    float rinv = rsqrtf(var + EPS);

    if (MODE == 2) {
        // output order n' = f*32 + dh ; buf/gamma index = dh*F + f
        for (int j2 = l; j2 < NEL; j2 += TPG) {
            int dh = j2 & 31, f = j2 >> 5;
            int jb = dh * F_ + f;
            float v = (buf[g * NEL + jb] - mu) * rinv * gamma[g * NEL + jb] + beta[g * NEL + jb];
            d_Vf[((size_t)(g * B_ + b) * TC + t) * DF + j2] = v;
        }
    } else {
        for (int j = l; j < NEL; j += TPG) {
            float v = (buf[g * NEL + j] - mu) * rinv * gamma[g * NEL + j] + beta[g * NEL + j];
            if (MODE == 1) {
                size_t idx = ((size_t)(g * B_ + b) * TC + t) * EF + j;
                float h = bfhi(v);
                d_KfH[idx] = __float2bfloat16(h);
                d_KfL[idx] = __float2bfloat16(v - h);
            } else {
                int r = j / F_, f = j - r * F_;
                outp[((size_t)(b * C_ + r) * T_ + t) * F_ + f] = v;
            }
        }
    }
}

// ---------------- 6) transpose Vf [z,tc,n'] -> VfTH/L [z,n',tc(pad416 zeros)] ----------
__global__ void transpose_v_kernel() {
    __shared__ float tile[32][33];
    int z = blockIdx.z;
    int n0 = blockIdx.x * 32, t0 = blockIdx.y * 32;
    int tx = threadIdx.x, ty = threadIdx.y;   // (32, 8)
#pragma unroll
    for (int i = ty; i < 32; i += 8) {
        int t = t0 + i;
        float v = 0.f;
        if (t < TC) v = d_Vf[((size_t)z * TC + t) * DF + n0 + tx];
        tile[i][tx] = v;
    }
    __syncthreads();
#pragma unroll
    for (int i = ty; i < 32; i += 8) {
        int n = n0 + i, t = t0 + tx;
        float v = tile[tx][i];
        float h = bfhi(v);
        size_t idx = ((size_t)z * DF + n) * PLD + t;
        d_VfTH[idx] = __float2bfloat16(h);
        d_VfTL[idx] = __float2bfloat16(v - h);
    }
}

// ---------------- 7) softmax on d_P rows -> PH/PL (pad cols zeroed) ----------------
__global__ void __launch_bounds__(128) softmax_kernel() {
    size_t row = blockIdx.x;
    const float* p = d_P + row * PLD;
    __nv_bfloat16* oh = d_PH + row * PLD;
    __nv_bfloat16* ol = d_PL + row * PLD;
    int tid = threadIdx.x;
    float v[4];
    int cnt = 0;
    float mx = -3.4e38f;
    for (int i = tid; i < TC; i += 128) { float x = p[i]; v[cnt++] = x; mx = fmaxf(mx, x); }
    __shared__ float smax[4], ssum[4];
#pragma unroll
    for (int o = 16; o > 0; o >>= 1) mx = fmaxf(mx, __shfl_xor_sync(0xffffffffu, mx, o));
    if ((tid & 31) == 0) smax[tid >> 5] = mx;
    __syncthreads();
    mx = fmaxf(fmaxf(smax[0], smax[1]), fmaxf(smax[2], smax[3]));
    float s = 0.f;
    for (int k = 0; k < cnt; k++) { float e = __expf(v[k] - mx); v[k] = e; s += e; }
#pragma unroll
    for (int o = 16; o > 0; o >>= 1) s += __shfl_xor_sync(0xffffffffu, s, o);
    if ((tid & 31) == 0) ssum[tid >> 5] = s;
    __syncthreads();
    s = ssum[0] + ssum[1] + ssum[2] + ssum[3];
    float inv = 1.f / s;
    cnt = 0;
    for (int i = tid; i < TC; i += 128) {
        float val = v[cnt++] * inv;
        float h = bfhi(val);
        oh[i] = __float2bfloat16(h);
        ol[i] = __float2bfloat16(val - h);
    }
    int ip = TC + tid;
    if (ip < PLD) { oh[ip] = __float2bfloat16(0.f); ol[ip] = __float2bfloat16(0.f); }
}

// ---------------- launch ----------------
extern "C" void kernel_launch(void* const* d_in, const int* in_sizes, int n_in,
                              void* d_out, int out_size) {
    (void)in_sizes; (void)n_in; (void)out_size;
    const float* batch = (const float*)d_in[0];
    const float* pos   = (const float*)d_in[1];
    const float* neg   = (const float*)d_in[2];
    const float* WQ  = (const float*)d_in[3];
    const float* bQ  = (const float*)d_in[4];
    const float* aQ  = (const float*)d_in[5];
    const float* gQ  = (const float*)d_in[6];
    const float* btQ = (const float*)d_in[7];
    const float* WK  = (const float*)d_in[8];
    const float* bK  = (const float*)d_in[9];
    const float* aK  = (const float*)d_in[10];
    const float* gK  = (const float*)d_in[11];
    const float* btK = (const float*)d_in[12];
    const float* WV  = (const float*)d_in[13];
    const float* bV  = (const float*)d_in[14];
    const float* aV  = (const float*)d_in[15];
    const float* gV  = (const float*)d_in[16];
    const float* btV = (const float*)d_in[17];
    const float* Wp  = (const float*)d_in[18];
    const float* bp  = (const float*)d_in[19];
    const float* ap  = (const float*)d_in[20];
    const float* gp  = (const float*)d_in[21];
    const float* btp = (const float*)d_in[22];
    float* out = (float*)d_out;

    void *pXTcH, *pXTcL, *pWKH, *pWKL, *pWVH, *pWVL, *pWpH, *pWpL;
    void *pQfH, *pQfL, *pKfH, *pKfL, *pVfTH, *pVfTL, *pPH, *pPL, *pOH, *pOL;
    void *pYk, *pYv, *pYp, *pP;
    cudaGetSymbolAddress(&pXTcH, d_XTcH); cudaGetSymbolAddress(&pXTcL, d_XTcL);
    cudaGetSymbolAddress(&pWKH, d_WKH);   cudaGetSymbolAddress(&pWKL, d_WKL);
    cudaGetSymbolAddress(&pWVH, d_WVH);   cudaGetSymbolAddress(&pWVL, d_WVL);
    cudaGetSymbolAddress(&pWpH, d_WpH);   cudaGetSymbolAddress(&pWpL, d_WpL);
    cudaGetSymbolAddress(&pQfH, d_QfH);   cudaGetSymbolAddress(&pQfL, d_QfL);
    cudaGetSymbolAddress(&pKfH, d_KfH);   cudaGetSymbolAddress(&pKfL, d_KfL);
    cudaGetSymbolAddress(&pVfTH, d_VfTH); cudaGetSymbolAddress(&pVfTL, d_VfTL);
    cudaGetSymbolAddress(&pPH, d_PH);     cudaGetSymbolAddress(&pPL, d_PL);
    cudaGetSymbolAddress(&pOH, d_OH);     cudaGetSymbolAddress(&pOL, d_OL);
    cudaGetSymbolAddress(&pYk, d_Yk);     cudaGetSymbolAddress(&pYv, d_Yv);
    cudaGetSymbolAddress(&pYp, d_Yp);     cudaGetSymbolAddress(&pP, d_P);

    typedef const __nv_bfloat16* BFP;
    typedef __nv_bfloat16* BFPW;

    const size_t smQK = (size_t)(C_ * F_ + 32 * 130) * sizeof(float);
    const size_t smMMA = 2 * 4 * (128 * 40 * 2);   // 81,920 B
    cudaFuncSetAttribute(conv_ln_q, cudaFuncAttributeMaxDynamicSharedMemorySize, (int)smQK);
    cudaFuncSetAttribute(mma_gemm<0, 0>, cudaFuncAttributeMaxDynamicSharedMemorySize, (int)smMMA);
    cudaFuncSetAttribute(mma_gemm<0, 1>, cudaFuncAttributeMaxDynamicSharedMemorySize, (int)smMMA);
    cudaFuncSetAttribute(mma_gemm<1, 0>, cudaFuncAttributeMaxDynamicSharedMemorySize, (int)smMMA);

    {   // 5-sums (input read once)
        int total2 = 2 * B_ * C_ * NB5 * F_;
        pool5_kernel<<<(total2 + 255) / 256, 256>>>(pos, neg);
    }
    {   // assemble XTc hi/lo
        dim3 g((NTFC + 31) / 32, C_ / 32, B_);
        xtc_kernel<<<g, dim3(32, 8)>>>();
    }
    wsplit_kernel<<<144, 256>>>(WK, WV, Wp);
    conv_ln_q<<<B_ * T_, 208, smQK>>>(batch, WQ, bQ, aQ, gQ, btQ);

    {   // K conv GEMM: Yk[b][oc<32][ntf]
        dim3 g((NTFC + 127) / 128, 1, B_);
        mma_gemm<0, 0><<<g, 256, smMMA>>>((BFP)pWKH, (BFP)pWKL, (BFP)pXTcH, (BFP)pXTcL,
            (float*)pYk, nullptr, nullptr,
            32, NTFC, C_, 4, C_, C_, NTFC,
            0LL, (long long)NTFC * C_, (long long)32 * NTFC, NTFC);
    }
    {   // V conv GEMM: Yv[b][oc<128][ntf]
        dim3 g((NTFC + 127) / 128, 1, B_);
        mma_gemm<0, 0><<<g, 256, smMMA>>>((BFP)pWVH, (BFP)pWVL, (BFP)pXTcH, (BFP)pXTcL,
            (float*)pYv, nullptr, nullptr,
            C_, NTFC, C_, 4, C_, C_, NTFC,
            0LL, (long long)NTFC * C_, (long long)C_ * NTFC, NTFC);
    }
    ln_kernel<32, 4, 1><<<B_ * TC, 256>>>((const float*)pYk, NTFC, bK, aK, gK, btK, nullptr);
    ln_kernel<128, 4, 2><<<B_ * TC, 256>>>((const float*)pYv, NTFC, bV, aV, gV, btV, nullptr);
    {   // Vf -> VfT hi/lo
        dim3 g(DF / 32, PLD / 32, H_ * B_);
        transpose_v_kernel<<<g, dim3(32, 8)>>>();
    }
    {   // scores: P = Qf @ Kf^T (fp32 out)
        dim3 g(4, 8, H_ * B_);
        mma_gemm<0, 0><<<g, 256, smMMA>>>((BFP)pQfH, (BFP)pQfL, (BFP)pKfH, (BFP)pKfL,
            (float*)pP, nullptr, nullptr,
            T_, TC, EF, 17, EF, EF, PLD,
            (long long)T_ * EF, (long long)TC * EF, (long long)T_ * PLD, PLD);
    }
    softmax_kernel<<<H_ * B_ * T_, 128>>>();
    {   // attention out: O' = P @ VfT^T  (bf16 hi/lo out, [z,t,n'=f*32+dh])
        dim3 g((DF + 127) / 128, 8, H_ * B_);
        mma_gemm<0, 1><<<g, 256, smMMA>>>((BFP)pPH, (BFP)pPL, (BFP)pVfTH, (BFP)pVfTL,
            nullptr, (BFPW)pOH, (BFPW)pOL,
            T_, DF, PLD, 13, PLD, PLD, DF,
            (long long)T_ * PLD, (long long)DF * PLD, (long long)T_ * DF, DF);
    }
    {   // proj GEMM (B gathered from O'): Yp[b][e][ntf]
        dim3 g((NTFT + 127) / 128, 1, B_);
        mma_gemm<1, 0><<<g, 256, smMMA>>>((BFP)pWpH, (BFP)pWpL, nullptr, nullptr,
            (float*)pYp, nullptr, nullptr,
            C_, NTFT, C_, 4, C_, 0, NTFT,
            0LL, 0LL, (long long)C_ * NTFT, NTFT);
    }
    ln_kernel<128, 1, 3><<<B_ * T_, 256>>>((const float*)pYp, NTFT, bp, ap, gp, btp, out);
}